// round 15
// baseline (speedup 1.0000x reference)
#include <cuda_runtime.h>
#include <cuda_fp16.h>

#define NMAX 131072
#define CAP 128

__device__ __align__(16) __half g_hA[NMAX * 16];
__device__ __align__(16) __half g_hB[NMAX * 16];
__device__ float g_nrmA[NMAX];   // inverse norm of hA (0 if ||h||==0)
__device__ float g_nrmB[NMAX];
__device__ int g_cnt[NMAX];      // zeroed by conv pass 1 epilogue (invariant)
__device__ int g_bkt[NMAX * CAP];
__device__ __align__(16) float g_v[20];
__device__ int g_idx64;

__device__ __forceinline__ unsigned int packh2(float a, float b) {
    __half2 t = __floats2half2_rn(a, b);
    return *(unsigned int*)&t;
}
__device__ __forceinline__ void unpack4(uint2 u, float* f) {
    float2 t;
    t = __half22float2(*(const __half2*)&u.x); f[0] = t.x; f[1] = t.y;
    t = __half22float2(*(const __half2*)&u.y); f[2] = t.x; f[3] = t.y;
}

// ---------------------------------------------------------------------------
// Aux kernel (no large smem -> full occupancy for scatter):
//   block 0          : fold lin2/gather into v[17]
//   blocks (0, gb]   : y init
//   blocks (gb, ...) : edge bucket scatter (g_cnt assumed zero on entry)
// ---------------------------------------------------------------------------
__global__ void __launch_bounds__(256) aux_kernel(
        const float* __restrict__ lin2_w, const float* __restrict__ lin2_b,
        const float* __restrict__ gather_w, const float* __restrict__ gather_b,
        float* __restrict__ y, const void* __restrict__ ei, long long E,
        int g, int gb) {
    int blk = blockIdx.x;
    int tid = threadIdx.x;

    if (blk == 0) {
        if (tid < 16) {
            float s = 0.f;
            #pragma unroll
            for (int j = 0; j < 64; j++) s += gather_w[j] * lin2_w[j * 16 + tid];
            g_v[tid] = s;
        } else if (tid == 16) {
            float s = 0.f;
            #pragma unroll
            for (int j = 0; j < 64; j++) s += gather_w[j] * lin2_b[j];
            g_v[16] = s;
        }
        return;
    }
    if (blk <= gb) {
        int i = (blk - 1) * 256 + tid;
        if (i < g) y[i] = gather_b[0];
        return;
    }

    // ---- scatter role ----
    __shared__ int sany;
    if (tid == 0) sany = 0;
    __syncthreads();
    {
        const unsigned int* raw = (const unsigned int*)ei;
        unsigned int v = raw[2 * tid + 1] | raw[2 * (tid + 256) + 1];
        if (v) atomicOr(&sany, 1);
    }
    __syncthreads();
    int idx64 = (sany == 0) ? 1 : 0;
    long long sblk = blk - gb - 1;
    if (sblk == 0 && tid == 0) g_idx64 = idx64;

    long long i = sblk * 256 + tid;
    long long e = i * 2;
    if (e >= E) return;
    bool two = (e + 1 < E);
    int s0, s1 = 0, d0, d1 = 0;
    if (idx64) {
        const long long* sp = (const long long*)ei;
        const long long* dp = sp + E;
        if (two) {
            longlong2 sv = __ldg((const longlong2*)sp + i);
            longlong2 dv = __ldg((const longlong2*)dp + i);
            s0 = (int)sv.x; s1 = (int)sv.y; d0 = (int)dv.x; d1 = (int)dv.y;
        } else { s0 = (int)__ldg(sp + e); d0 = (int)__ldg(dp + e); }
    } else {
        const int* sp = (const int*)ei;
        const int* dp = sp + E;
        if (two) {
            int2 sv = __ldg((const int2*)sp + i);
            int2 dv = __ldg((const int2*)dp + i);
            s0 = sv.x; s1 = sv.y; d0 = dv.x; d1 = dv.y;
        } else { s0 = __ldg(sp + e); d0 = __ldg(dp + e); }
    }
    int p0 = atomicAdd(&g_cnt[d0], 1);
    if (p0 < CAP) g_bkt[((size_t)d0 << 7) + p0] = s0;
    if (two) {
        int p1 = atomicAdd(&g_cnt[d1], 1);
        if (p1 < CAP) g_bkt[((size_t)d1 << 7) + p1] = s1;
    }
}

// ---------------------------------------------------------------------------
// h = relu(x @ W1^T + b1) stored fp16 + inv-norm.
// 64 nodes/block, 4-way split-k (4 threads per node) -> ~24KB smem,
// 8 blocks/SM = full occupancy (vs 5 blocks at 43KB).
// ---------------------------------------------------------------------------
__global__ void __launch_bounds__(256) lin1_kernel(
        const float* __restrict__ x, const float* __restrict__ w,
        const float* __restrict__ b, int n) {
    __shared__ float sx[64 * 75];
    __shared__ float sw[75 * 16];
    __shared__ float sb[16];
    int tid = threadIdx.x;
    int bstart = blockIdx.x * 64;

    for (int i = tid; i < 75 * 16; i += 256) {
        int j = i / 75, k = i % 75;       // w is [16,75] row-major
        sw[k * 16 + j] = w[i];
    }
    if (tid < 16) sb[tid] = b[tid];

    int nodes = min(64, n - bstart);
    if (nodes == 64) {
        const float4* src = (const float4*)(x + (size_t)bstart * 75);
        float4* dst = (float4*)sx;
        #pragma unroll 2
        for (int i = tid; i < 64 * 75 / 4; i += 256) dst[i] = src[i];
    } else {
        for (int i = tid; i < nodes * 75; i += 256)
            sx[i] = x[(size_t)bstart * 75 + i];
    }
    __syncthreads();

    int node_l = tid >> 2;           // 0..63
    int quarter = tid & 3;           // split-k lane within node
    int node_c = min(node_l, nodes - 1);
    const float* row = sx + node_c * 75;
    const float4* swv = (const float4*)sw;

    float4 a0 = make_float4(0.f, 0.f, 0.f, 0.f);
    float4 a1 = a0, a2 = a0, a3 = a0;
    #pragma unroll 4
    for (int k = quarter; k < 75; k += 4) {
        float rk = row[k];
        float4 w0 = swv[k * 4 + 0];
        float4 w1 = swv[k * 4 + 1];
        float4 w2 = swv[k * 4 + 2];
        float4 w3 = swv[k * 4 + 3];
        a0.x += rk * w0.x; a0.y += rk * w0.y; a0.z += rk * w0.z; a0.w += rk * w0.w;
        a1.x += rk * w1.x; a1.y += rk * w1.y; a1.z += rk * w1.z; a1.w += rk * w1.w;
        a2.x += rk * w2.x; a2.y += rk * w2.y; a2.z += rk * w2.z; a2.w += rk * w2.w;
        a3.x += rk * w3.x; a3.y += rk * w3.y; a3.z += rk * w3.z; a3.w += rk * w3.w;
    }
    #pragma unroll
    for (int m = 1; m <= 2; m <<= 1) {
        a0.x += __shfl_xor_sync(0xffffffffu, a0.x, m);
        a0.y += __shfl_xor_sync(0xffffffffu, a0.y, m);
        a0.z += __shfl_xor_sync(0xffffffffu, a0.z, m);
        a0.w += __shfl_xor_sync(0xffffffffu, a0.w, m);
        a1.x += __shfl_xor_sync(0xffffffffu, a1.x, m);
        a1.y += __shfl_xor_sync(0xffffffffu, a1.y, m);
        a1.z += __shfl_xor_sync(0xffffffffu, a1.z, m);
        a1.w += __shfl_xor_sync(0xffffffffu, a1.w, m);
        a2.x += __shfl_xor_sync(0xffffffffu, a2.x, m);
        a2.y += __shfl_xor_sync(0xffffffffu, a2.y, m);
        a2.z += __shfl_xor_sync(0xffffffffu, a2.z, m);
        a2.w += __shfl_xor_sync(0xffffffffu, a2.w, m);
        a3.x += __shfl_xor_sync(0xffffffffu, a3.x, m);
        a3.y += __shfl_xor_sync(0xffffffffu, a3.y, m);
        a3.z += __shfl_xor_sync(0xffffffffu, a3.z, m);
        a3.w += __shfl_xor_sync(0xffffffffu, a3.w, m);
    }

    if (quarter || node_l >= nodes) return;
    int node = bstart + node_l;

    a0.x = fmaxf(a0.x + sb[0], 0.f);  a0.y = fmaxf(a0.y + sb[1], 0.f);
    a0.z = fmaxf(a0.z + sb[2], 0.f);  a0.w = fmaxf(a0.w + sb[3], 0.f);
    a1.x = fmaxf(a1.x + sb[4], 0.f);  a1.y = fmaxf(a1.y + sb[5], 0.f);
    a1.z = fmaxf(a1.z + sb[6], 0.f);  a1.w = fmaxf(a1.w + sb[7], 0.f);
    a2.x = fmaxf(a2.x + sb[8], 0.f);  a2.y = fmaxf(a2.y + sb[9], 0.f);
    a2.z = fmaxf(a2.z + sb[10], 0.f); a2.w = fmaxf(a2.w + sb[11], 0.f);
    a3.x = fmaxf(a3.x + sb[12], 0.f); a3.y = fmaxf(a3.y + sb[13], 0.f);
    a3.z = fmaxf(a3.z + sb[14], 0.f); a3.w = fmaxf(a3.w + sb[15], 0.f);

    float ss = a0.x*a0.x + a0.y*a0.y + a0.z*a0.z + a0.w*a0.w
             + a1.x*a1.x + a1.y*a1.y + a1.z*a1.z + a1.w*a1.w
             + a2.x*a2.x + a2.y*a2.y + a2.z*a2.z + a2.w*a2.w
             + a3.x*a3.x + a3.y*a3.y + a3.z*a3.z + a3.w*a3.w;
    g_nrmA[node] = (ss > 0.f) ? rsqrtf(ss) : 0.f;

    uint4 u0, u1;
    u0.x = packh2(a0.x, a0.y); u0.y = packh2(a0.z, a0.w);
    u0.z = packh2(a1.x, a1.y); u0.w = packh2(a1.z, a1.w);
    u1.x = packh2(a2.x, a2.y); u1.y = packh2(a2.z, a2.w);
    u1.z = packh2(a3.x, a3.y); u1.w = packh2(a3.z, a3.w);
    uint4* hp = (uint4*)g_hA + (size_t)node * 2;
    hp[0] = u0; hp[1] = u1;
}

// ---------------------------------------------------------------------------
// AGNN conv: FOUR nodes per warp (8 lanes each: 2 groups x 4 lanes/edge).
// Strided 2x unroll, branch-free; int2 paired idx loads.
// Post-loop: single m=4 reduction across the node's 2 groups.
// ---------------------------------------------------------------------------
__global__ void __launch_bounds__(256, 6) conv_kernel(int pass,
        const float* __restrict__ beta, const void* __restrict__ batchv,
        float* __restrict__ y, int n) {
    int warp_id = (blockIdx.x * blockDim.x + threadIdx.x) >> 5;
    int lane = threadIdx.x & 31;
    int c = lane & 3;           // component slice
    int grp = (lane >> 2) & 1;  // group within 8-lane section
    int nsub = lane >> 3;       // node sub-slot 0..3
    int node = warp_id * 4 + nsub;
    if (node >= n) return;      // other sections continue; shuffles are masked
    unsigned sm8 = 0xFFu << (nsub << 3);  // 8-lane section mask
    unsigned gm = 0xFu << (lane & 28);    // 4-lane group mask

    const uint2* hh = (const uint2*)(pass ? g_hB : g_hA);
    const float* nrm = pass ? g_nrmB : g_nrmA;
    float b0 = __ldg(beta);

    uint2 du = __ldg(hh + (size_t)node * 4 + c);
    float xd[4];
    unpack4(du, xd);
    float invd = __ldg(nrm + node);
    float cd = b0 * invd;

    int cnt = min(__ldg(g_cnt + node), CAP);
    const int* bkt = g_bkt + ((size_t)node << 7);

    float4 acc = make_float4(0.f, 0.f, 0.f, 0.f);
    float den = 0.f;

    // group g owns pairs {4k+2g, 4k+2g+1}; int2 loads are 8B-aligned.
    int jb = grp * 2;
    for (; jb + 1 < cnt; jb += 4) {
        int2 s2 = __ldg((const int2*)(bkt + jb));
        uint2 u0 = __ldg(hh + (size_t)s2.x * 4 + c);
        uint2 u1 = __ldg(hh + (size_t)s2.y * 4 + c);
        float i0 = __ldg(nrm + s2.x);
        float i1 = __ldg(nrm + s2.y);
        float h0[4], h1[4];
        unpack4(u0, h0);
        unpack4(u1, h1);
        float dot0 = h0[0]*xd[0] + h0[1]*xd[1] + h0[2]*xd[2] + h0[3]*xd[3];
        float dot1 = h1[0]*xd[0] + h1[1]*xd[1] + h1[2]*xd[2] + h1[3]*xd[3];
        dot0 += __shfl_xor_sync(gm, dot0, 1);
        dot1 += __shfl_xor_sync(gm, dot1, 1);
        dot0 += __shfl_xor_sync(gm, dot0, 2);
        dot1 += __shfl_xor_sync(gm, dot1, 2);
        float ex0 = __expf(dot0 * i0 * cd);
        float ex1 = __expf(dot1 * i1 * cd);
        acc.x += ex0 * h0[0] + ex1 * h1[0];
        acc.y += ex0 * h0[1] + ex1 * h1[1];
        acc.z += ex0 * h0[2] + ex1 * h1[2];
        acc.w += ex0 * h0[3] + ex1 * h1[3];
        den += ex0 + ex1;
    }
    if (jb < cnt) {
        int s0 = __ldg(bkt + jb);
        uint2 u0 = __ldg(hh + (size_t)s0 * 4 + c);
        float i0 = __ldg(nrm + s0);
        float h0[4];
        unpack4(u0, h0);
        float dot0 = h0[0]*xd[0] + h0[1]*xd[1] + h0[2]*xd[2] + h0[3]*xd[3];
        dot0 += __shfl_xor_sync(gm, dot0, 1);
        dot0 += __shfl_xor_sync(gm, dot0, 2);
        float ex0 = __expf(dot0 * i0 * cd);
        acc.x += ex0 * h0[0]; acc.y += ex0 * h0[1];
        acc.z += ex0 * h0[2]; acc.w += ex0 * h0[3];
        den += ex0;
    }

    // reduce across the node's 2 groups (c-slice stays per-lane).
    // den identical across a group's 4 lanes -> single m=4 round suffices.
    acc.x += __shfl_xor_sync(sm8, acc.x, 4);
    acc.y += __shfl_xor_sync(sm8, acc.y, 4);
    acc.z += __shfl_xor_sync(sm8, acc.z, 4);
    acc.w += __shfl_xor_sync(sm8, acc.w, 4);
    den   += __shfl_xor_sync(sm8, den, 4);

    float exs = (invd > 0.f) ? __expf(b0) : 1.0f;
    float r = 1.f / (den + exs);
    float4 o = make_float4((acc.x + exs * xd[0]) * r, (acc.y + exs * xd[1]) * r,
                           (acc.z + exs * xd[2]) * r, (acc.w + exs * xd[3]) * r);

    if (pass == 0) {
        float ss = o.x*o.x + o.y*o.y + o.z*o.z + o.w*o.w;
        ss += __shfl_xor_sync(gm, ss, 1);
        ss += __shfl_xor_sync(gm, ss, 2);
        if (grp == 0) {
            uint2 u;
            u.x = packh2(o.x, o.y);
            u.y = packh2(o.z, o.w);
            ((uint2*)g_hB)[(size_t)node * 4 + c] = u;
            if ((lane & 7) == 0)
                g_nrmB[node] = (ss > 0.f) ? rsqrtf(ss) : 0.f;
        }
    } else {
        if (grp == 0) {
            float4 vc = __ldg((const float4*)g_v + c);
            float part = o.x * vc.x + o.y * vc.y + o.z * vc.z + o.w * vc.w;
            part += __shfl_xor_sync(gm, part, 1);
            part += __shfl_xor_sync(gm, part, 2);
            if ((lane & 7) == 0) {
                int b;
                if (g_idx64) b = (int)((const long long*)batchv)[node];
                else         b = ((const int*)batchv)[node];
                atomicAdd(y + b, part + g_v[16]);
                g_cnt[node] = 0;   // maintain zero-invariant for next launch
            }
        }
    }
}

extern "C" void kernel_launch(void* const* d_in, const int* in_sizes, int n_in,
                              void* d_out, int out_size) {
    const float* x     = (const float*)d_in[0];
    const void*  ei    = d_in[1];
    const void*  batch = d_in[2];
    int off = (in_sizes[3] == 16 * 75) ? 3 : 4;
    const float* lin1_w   = (const float*)d_in[off + 0];
    const float* lin1_b   = (const float*)d_in[off + 1];
    const float* beta1    = (const float*)d_in[off + 2];
    const float* beta2    = (const float*)d_in[off + 3];
    const float* lin2_w   = (const float*)d_in[off + 4];
    const float* lin2_b   = (const float*)d_in[off + 5];
    const float* gather_w = (const float*)d_in[off + 6];
    const float* gather_b = (const float*)d_in[off + 7];

    int n = in_sizes[0] / 75;
    long long E = (long long)in_sizes[1] / 2;
    int G = out_size;
    float* y = (float*)d_out;

    int gb = (G + 255) / 256;
    long long pairs = (E + 1) / 2;
    int sb = (int)((pairs + 255) / 256);

    aux_kernel<<<1 + gb + sb, 256>>>(lin2_w, lin2_b, gather_w, gather_b, y,
                                     ei, E, G, gb);
    lin1_kernel<<<(n + 63) / 64, 256>>>(x, lin1_w, lin1_b, n);

    int nwarps = (n + 3) / 4;
    int cblocks = (nwarps * 32 + 255) / 256;
    conv_kernel<<<cblocks, 256>>>(0, beta1, batch, y, n);
    conv_kernel<<<cblocks, 256>>>(1, beta2, batch, y, n);
}

// round 16
// speedup vs baseline: 1.1537x; 1.1537x over previous
#include <cuda_runtime.h>
#include <cuda_fp16.h>

#define NMAX 131072
#define CAP 128

__device__ __align__(16) __half g_hA[NMAX * 16];
__device__ __align__(16) __half g_hB[NMAX * 16];
__device__ float g_nrmA[NMAX];   // inverse norm of hA (0 if ||h||==0)
__device__ float g_nrmB[NMAX];
__device__ int g_cnt[NMAX];      // zeroed by conv pass 1 epilogue (invariant)
__device__ int g_bkt[NMAX * CAP];
__device__ __align__(16) float g_v[20];
__device__ int g_idx64;

__device__ __forceinline__ unsigned int packh2(float a, float b) {
    __half2 t = __floats2half2_rn(a, b);
    return *(unsigned int*)&t;
}
__device__ __forceinline__ void unpack4(uint2 u, float* f) {
    float2 t;
    t = __half22float2(*(const __half2*)&u.x); f[0] = t.x; f[1] = t.y;
    t = __half22float2(*(const __half2*)&u.y); f[2] = t.x; f[3] = t.y;
}

// ---------------------------------------------------------------------------
// Aux kernel (no large smem -> full occupancy for scatter):
//   block 0          : fold lin2/gather into v[17]
//   blocks (0, gb]   : y init
//   blocks (gb, ...) : edge bucket scatter (g_cnt assumed zero on entry)
// ---------------------------------------------------------------------------
__global__ void __launch_bounds__(256) aux_kernel(
        const float* __restrict__ lin2_w, const float* __restrict__ lin2_b,
        const float* __restrict__ gather_w, const float* __restrict__ gather_b,
        float* __restrict__ y, const void* __restrict__ ei, long long E,
        int g, int gb) {
    int blk = blockIdx.x;
    int tid = threadIdx.x;

    if (blk == 0) {
        if (tid < 16) {
            float s = 0.f;
            #pragma unroll
            for (int j = 0; j < 64; j++) s += gather_w[j] * lin2_w[j * 16 + tid];
            g_v[tid] = s;
        } else if (tid == 16) {
            float s = 0.f;
            #pragma unroll
            for (int j = 0; j < 64; j++) s += gather_w[j] * lin2_b[j];
            g_v[16] = s;
        }
        return;
    }
    if (blk <= gb) {
        int i = (blk - 1) * 256 + tid;
        if (i < g) y[i] = gather_b[0];
        return;
    }

    // ---- scatter role ----
    __shared__ int sany;
    if (tid == 0) sany = 0;
    __syncthreads();
    {
        const unsigned int* raw = (const unsigned int*)ei;
        unsigned int v = raw[2 * tid + 1] | raw[2 * (tid + 256) + 1];
        if (v) atomicOr(&sany, 1);
    }
    __syncthreads();
    int idx64 = (sany == 0) ? 1 : 0;
    long long sblk = blk - gb - 1;
    if (sblk == 0 && tid == 0) g_idx64 = idx64;

    long long i = sblk * 256 + tid;
    long long e = i * 2;
    if (e >= E) return;
    bool two = (e + 1 < E);
    int s0, s1 = 0, d0, d1 = 0;
    if (idx64) {
        const long long* sp = (const long long*)ei;
        const long long* dp = sp + E;
        if (two) {
            longlong2 sv = __ldg((const longlong2*)sp + i);
            longlong2 dv = __ldg((const longlong2*)dp + i);
            s0 = (int)sv.x; s1 = (int)sv.y; d0 = (int)dv.x; d1 = (int)dv.y;
        } else { s0 = (int)__ldg(sp + e); d0 = (int)__ldg(dp + e); }
    } else {
        const int* sp = (const int*)ei;
        const int* dp = sp + E;
        if (two) {
            int2 sv = __ldg((const int2*)sp + i);
            int2 dv = __ldg((const int2*)dp + i);
            s0 = sv.x; s1 = sv.y; d0 = dv.x; d1 = dv.y;
        } else { s0 = __ldg(sp + e); d0 = __ldg(dp + e); }
    }
    int p0 = atomicAdd(&g_cnt[d0], 1);
    if (p0 < CAP) g_bkt[((size_t)d0 << 7) + p0] = s0;
    if (two) {
        int p1 = atomicAdd(&g_cnt[d1], 1);
        if (p1 < CAP) g_bkt[((size_t)d1 << 7) + p1] = s1;
    }
}

// ---------------------------------------------------------------------------
// h = relu(x @ W1^T + b1) stored fp16 + inv-norm. Split-k lane pairs.
// (128 nodes/block, 43KB smem — empirically faster than the 64-node
//  "higher-occupancy" variant; verified R12 configuration.)
// ---------------------------------------------------------------------------
__global__ void __launch_bounds__(256) lin1_kernel(
        const float* __restrict__ x, const float* __restrict__ w,
        const float* __restrict__ b, int n) {
    __shared__ float sx[128 * 75];
    __shared__ float sw[75 * 16];
    __shared__ float sb[16];
    int tid = threadIdx.x;
    int bstart = blockIdx.x * 128;

    for (int i = tid; i < 75 * 16; i += 256) {
        int j = i / 75, k = i % 75;       // w is [16,75] row-major
        sw[k * 16 + j] = w[i];
    }
    if (tid < 16) sb[tid] = b[tid];

    int nodes = min(128, n - bstart);
    if (nodes == 128) {
        const float4* src = (const float4*)(x + (size_t)bstart * 75);
        float4* dst = (float4*)sx;
        #pragma unroll 4
        for (int i = tid; i < 128 * 75 / 4; i += 256) dst[i] = src[i];
    } else {
        for (int i = tid; i < nodes * 75; i += 256)
            sx[i] = x[(size_t)bstart * 75 + i];
    }
    __syncthreads();

    int node_l = tid >> 1;
    int half = tid & 1;
    int node_c = min(node_l, nodes - 1);
    const float* row = sx + node_c * 75;
    const float4* swv = (const float4*)sw;

    float4 a0 = make_float4(0.f, 0.f, 0.f, 0.f);
    float4 a1 = a0, a2 = a0, a3 = a0;
    #pragma unroll 4
    for (int k = half; k < 75; k += 2) {
        float rk = row[k];
        float4 w0 = swv[k * 4 + 0];
        float4 w1 = swv[k * 4 + 1];
        float4 w2 = swv[k * 4 + 2];
        float4 w3 = swv[k * 4 + 3];
        a0.x += rk * w0.x; a0.y += rk * w0.y; a0.z += rk * w0.z; a0.w += rk * w0.w;
        a1.x += rk * w1.x; a1.y += rk * w1.y; a1.z += rk * w1.z; a1.w += rk * w1.w;
        a2.x += rk * w2.x; a2.y += rk * w2.y; a2.z += rk * w2.z; a2.w += rk * w2.w;
        a3.x += rk * w3.x; a3.y += rk * w3.y; a3.z += rk * w3.z; a3.w += rk * w3.w;
    }
    a0.x += __shfl_xor_sync(0xffffffffu, a0.x, 1);
    a0.y += __shfl_xor_sync(0xffffffffu, a0.y, 1);
    a0.z += __shfl_xor_sync(0xffffffffu, a0.z, 1);
    a0.w += __shfl_xor_sync(0xffffffffu, a0.w, 1);
    a1.x += __shfl_xor_sync(0xffffffffu, a1.x, 1);
    a1.y += __shfl_xor_sync(0xffffffffu, a1.y, 1);
    a1.z += __shfl_xor_sync(0xffffffffu, a1.z, 1);
    a1.w += __shfl_xor_sync(0xffffffffu, a1.w, 1);
    a2.x += __shfl_xor_sync(0xffffffffu, a2.x, 1);
    a2.y += __shfl_xor_sync(0xffffffffu, a2.y, 1);
    a2.z += __shfl_xor_sync(0xffffffffu, a2.z, 1);
    a2.w += __shfl_xor_sync(0xffffffffu, a2.w, 1);
    a3.x += __shfl_xor_sync(0xffffffffu, a3.x, 1);
    a3.y += __shfl_xor_sync(0xffffffffu, a3.y, 1);
    a3.z += __shfl_xor_sync(0xffffffffu, a3.z, 1);
    a3.w += __shfl_xor_sync(0xffffffffu, a3.w, 1);

    if (half || node_l >= nodes) return;
    int node = bstart + node_l;

    a0.x = fmaxf(a0.x + sb[0], 0.f);  a0.y = fmaxf(a0.y + sb[1], 0.f);
    a0.z = fmaxf(a0.z + sb[2], 0.f);  a0.w = fmaxf(a0.w + sb[3], 0.f);
    a1.x = fmaxf(a1.x + sb[4], 0.f);  a1.y = fmaxf(a1.y + sb[5], 0.f);
    a1.z = fmaxf(a1.z + sb[6], 0.f);  a1.w = fmaxf(a1.w + sb[7], 0.f);
    a2.x = fmaxf(a2.x + sb[8], 0.f);  a2.y = fmaxf(a2.y + sb[9], 0.f);
    a2.z = fmaxf(a2.z + sb[10], 0.f); a2.w = fmaxf(a2.w + sb[11], 0.f);
    a3.x = fmaxf(a3.x + sb[12], 0.f); a3.y = fmaxf(a3.y + sb[13], 0.f);
    a3.z = fmaxf(a3.z + sb[14], 0.f); a3.w = fmaxf(a3.w + sb[15], 0.f);

    float ss = a0.x*a0.x + a0.y*a0.y + a0.z*a0.z + a0.w*a0.w
             + a1.x*a1.x + a1.y*a1.y + a1.z*a1.z + a1.w*a1.w
             + a2.x*a2.x + a2.y*a2.y + a2.z*a2.z + a2.w*a2.w
             + a3.x*a3.x + a3.y*a3.y + a3.z*a3.z + a3.w*a3.w;
    g_nrmA[node] = (ss > 0.f) ? rsqrtf(ss) : 0.f;

    uint4 u0, u1;
    u0.x = packh2(a0.x, a0.y); u0.y = packh2(a0.z, a0.w);
    u0.z = packh2(a1.x, a1.y); u0.w = packh2(a1.z, a1.w);
    u1.x = packh2(a2.x, a2.y); u1.y = packh2(a2.z, a2.w);
    u1.z = packh2(a3.x, a3.y); u1.w = packh2(a3.z, a3.w);
    uint4* hp = (uint4*)g_hA + (size_t)node * 2;
    hp[0] = u0; hp[1] = u1;
}

// ---------------------------------------------------------------------------
// AGNN conv: FOUR nodes per warp (8 lanes each: 2 groups x 4 lanes/edge).
// Strided 2x unroll, branch-free; int2 paired idx loads.
// Post-loop: single m=4 reduction across the node's 2 groups.
// ---------------------------------------------------------------------------
__global__ void __launch_bounds__(256, 6) conv_kernel(int pass,
        const float* __restrict__ beta, const void* __restrict__ batchv,
        float* __restrict__ y, int n) {
    int warp_id = (blockIdx.x * blockDim.x + threadIdx.x) >> 5;
    int lane = threadIdx.x & 31;
    int c = lane & 3;           // component slice
    int grp = (lane >> 2) & 1;  // group within 8-lane section
    int nsub = lane >> 3;       // node sub-slot 0..3
    int node = warp_id * 4 + nsub;
    if (node >= n) return;      // other sections continue; shuffles are masked
    unsigned sm8 = 0xFFu << (nsub << 3);  // 8-lane section mask
    unsigned gm = 0xFu << (lane & 28);    // 4-lane group mask

    const uint2* hh = (const uint2*)(pass ? g_hB : g_hA);
    const float* nrm = pass ? g_nrmB : g_nrmA;
    float b0 = __ldg(beta);

    uint2 du = __ldg(hh + (size_t)node * 4 + c);
    float xd[4];
    unpack4(du, xd);
    float invd = __ldg(nrm + node);
    float cd = b0 * invd;

    int cnt = min(__ldg(g_cnt + node), CAP);
    const int* bkt = g_bkt + ((size_t)node << 7);

    float4 acc = make_float4(0.f, 0.f, 0.f, 0.f);
    float den = 0.f;

    // group g owns pairs {4k+2g, 4k+2g+1}; int2 loads are 8B-aligned.
    int jb = grp * 2;
    for (; jb + 1 < cnt; jb += 4) {
        int2 s2 = __ldg((const int2*)(bkt + jb));
        uint2 u0 = __ldg(hh + (size_t)s2.x * 4 + c);
        uint2 u1 = __ldg(hh + (size_t)s2.y * 4 + c);
        float i0 = __ldg(nrm + s2.x);
        float i1 = __ldg(nrm + s2.y);
        float h0[4], h1[4];
        unpack4(u0, h0);
        unpack4(u1, h1);
        float dot0 = h0[0]*xd[0] + h0[1]*xd[1] + h0[2]*xd[2] + h0[3]*xd[3];
        float dot1 = h1[0]*xd[0] + h1[1]*xd[1] + h1[2]*xd[2] + h1[3]*xd[3];
        dot0 += __shfl_xor_sync(gm, dot0, 1);
        dot1 += __shfl_xor_sync(gm, dot1, 1);
        dot0 += __shfl_xor_sync(gm, dot0, 2);
        dot1 += __shfl_xor_sync(gm, dot1, 2);
        float ex0 = __expf(dot0 * i0 * cd);
        float ex1 = __expf(dot1 * i1 * cd);
        acc.x += ex0 * h0[0] + ex1 * h1[0];
        acc.y += ex0 * h0[1] + ex1 * h1[1];
        acc.z += ex0 * h0[2] + ex1 * h1[2];
        acc.w += ex0 * h0[3] + ex1 * h1[3];
        den += ex0 + ex1;
    }
    if (jb < cnt) {
        int s0 = __ldg(bkt + jb);
        uint2 u0 = __ldg(hh + (size_t)s0 * 4 + c);
        float i0 = __ldg(nrm + s0);
        float h0[4];
        unpack4(u0, h0);
        float dot0 = h0[0]*xd[0] + h0[1]*xd[1] + h0[2]*xd[2] + h0[3]*xd[3];
        dot0 += __shfl_xor_sync(gm, dot0, 1);
        dot0 += __shfl_xor_sync(gm, dot0, 2);
        float ex0 = __expf(dot0 * i0 * cd);
        acc.x += ex0 * h0[0]; acc.y += ex0 * h0[1];
        acc.z += ex0 * h0[2]; acc.w += ex0 * h0[3];
        den += ex0;
    }

    // reduce across the node's 2 groups (c-slice stays per-lane).
    // den identical across a group's 4 lanes -> single m=4 round suffices.
    acc.x += __shfl_xor_sync(sm8, acc.x, 4);
    acc.y += __shfl_xor_sync(sm8, acc.y, 4);
    acc.z += __shfl_xor_sync(sm8, acc.z, 4);
    acc.w += __shfl_xor_sync(sm8, acc.w, 4);
    den   += __shfl_xor_sync(sm8, den, 4);

    float exs = (invd > 0.f) ? __expf(b0) : 1.0f;
    float r = 1.f / (den + exs);
    float4 o = make_float4((acc.x + exs * xd[0]) * r, (acc.y + exs * xd[1]) * r,
                           (acc.z + exs * xd[2]) * r, (acc.w + exs * xd[3]) * r);

    if (pass == 0) {
        float ss = o.x*o.x + o.y*o.y + o.z*o.z + o.w*o.w;
        ss += __shfl_xor_sync(gm, ss, 1);
        ss += __shfl_xor_sync(gm, ss, 2);
        if (grp == 0) {
            uint2 u;
            u.x = packh2(o.x, o.y);
            u.y = packh2(o.z, o.w);
            ((uint2*)g_hB)[(size_t)node * 4 + c] = u;
            if ((lane & 7) == 0)
                g_nrmB[node] = (ss > 0.f) ? rsqrtf(ss) : 0.f;
        }
    } else {
        if (grp == 0) {
            float4 vc = __ldg((const float4*)g_v + c);
            float part = o.x * vc.x + o.y * vc.y + o.z * vc.z + o.w * vc.w;
            part += __shfl_xor_sync(gm, part, 1);
            part += __shfl_xor_sync(gm, part, 2);
            if ((lane & 7) == 0) {
                int b;
                if (g_idx64) b = (int)((const long long*)batchv)[node];
                else         b = ((const int*)batchv)[node];
                atomicAdd(y + b, part + g_v[16]);
                g_cnt[node] = 0;   // maintain zero-invariant for next launch
            }
        }
    }
}

extern "C" void kernel_launch(void* const* d_in, const int* in_sizes, int n_in,
                              void* d_out, int out_size) {
    const float* x     = (const float*)d_in[0];
    const void*  ei    = d_in[1];
    const void*  batch = d_in[2];
    int off = (in_sizes[3] == 16 * 75) ? 3 : 4;
    const float* lin1_w   = (const float*)d_in[off + 0];
    const float* lin1_b   = (const float*)d_in[off + 1];
    const float* beta1    = (const float*)d_in[off + 2];
    const float* beta2    = (const float*)d_in[off + 3];
    const float* lin2_w   = (const float*)d_in[off + 4];
    const float* lin2_b   = (const float*)d_in[off + 5];
    const float* gather_w = (const float*)d_in[off + 6];
    const float* gather_b = (const float*)d_in[off + 7];

    int n = in_sizes[0] / 75;
    long long E = (long long)in_sizes[1] / 2;
    int G = out_size;
    float* y = (float*)d_out;

    int gb = (G + 255) / 256;
    long long pairs = (E + 1) / 2;
    int sb = (int)((pairs + 255) / 256);

    aux_kernel<<<1 + gb + sb, 256>>>(lin2_w, lin2_b, gather_w, gather_b, y,
                                     ei, E, G, gb);
    lin1_kernel<<<(n + 127) / 128, 256>>>(x, lin1_w, lin1_b, n);

    int nwarps = (n + 3) / 4;
    int cblocks = (nwarps * 32 + 255) / 256;
    conv_kernel<<<cblocks, 256>>>(0, beta1, batch, y, n);
    conv_kernel<<<cblocks, 256>>>(1, beta2, batch, y, n);
}